// round 5
// baseline (speedup 1.0000x reference)
#include <cuda_runtime.h>
#include <cstdint>

#define BATCH 64
#define NTOK  65536            // 256*256
#define KSEL  16384
#define TOTAL (BATCH * NTOK)
#define CANDCAP 4096           // per-batch candidate capacity (global)
#define CANDB   384            // per-block candidate capacity (smem)
#define GBLK    1024           // gather blocks (16 per batch)
#define BPB     16             // blocks per batch

// ---- device scratch (device globals; no allocations) ----
__device__ uint32_t g_cand[BATCH * CANDCAP];
__device__ uint32_t g_nc[BATCH];     // candidate counts (zero-init; reset by finalize)
__device__ uint32_t g_c2[BATCH];     // counts >= P2     (zero-init; reset by finalize)
__device__ uint32_t g_of[BATCH];     // overflow flags   (zero-init; reset by finalize)
__device__ uint32_t g_tick[BATCH];   // per-batch gather-done tickets (reset by finalize)
__device__ uint32_t g_T[BATCH];      // threshold bit pattern
__device__ uint32_t g_req[BATCH];    // #(==T) to include
__device__ uint32_t g_eqcnt[BATCH];  // runtime tie counter
__device__ double   g_acc;           // loss accumulator
__device__ unsigned g_done;          // finalize ticket

#define P1F 0.73f
#define P2F 0.77f

// exclusive suffix sum over 256 threads (sum of v for tid' > tid)
__device__ __forceinline__ uint32_t suffix_excl_256(uint32_t v, uint32_t* wsum) {
    const int t = threadIdx.x, lane = t & 31, w = t >> 5;
    uint32_t s = v;
    #pragma unroll
    for (int off = 1; off < 32; off <<= 1) {
        uint32_t o = __shfl_down_sync(0xFFFFFFFFu, s, off);
        if (lane + off < 32) s += o;
    }
    if (lane == 0) wsum[w] = s;
    __syncthreads();
    if (t == 0) {
        uint32_t run = 0;
        for (int i = 7; i >= 0; i--) { uint32_t x = wsum[i]; wsum[i] = run; run += x; }
    }
    __syncthreads();
    return wsum[w] + (s - v);   // suffix of warps after mine + suffix within my warp
}

// ============================================================================
// Kernel 1: smap sweep (16 MB) + fused per-batch threshold select.
//  Phase A (all 1024 blocks): count u>=P2; gather P1<=u<P2 candidates with a
//  block prefix-sum (ZERO atomics on the hot path).
//  Phase B (last block per batch): 3-round radix select among candidates.
// ============================================================================
__global__ __launch_bounds__(256) void gather_thresh_kernel(const uint4* __restrict__ sm4,
                                                            const float* __restrict__ smap) {
    __shared__ uint32_t scand[CANDB];
    __shared__ uint32_t hist[2048];
    __shared__ uint32_t wsum[8];
    __shared__ uint32_t sTot, sBase, sBin, sK;

    const int t    = threadIdx.x;
    const int lane = t & 31;
    const int w    = t >> 5;
    const int b    = blockIdx.x >> 4;              // 16 blocks per batch
    const int blockBase = blockIdx.x * 1024;       // uint4-group base

    const uint32_t P1 = __float_as_uint(P1F);
    const uint32_t P2 = __float_as_uint(P2F);
    const uint32_t W  = P2 - P1;                   // window width (bit space)

    // ---- Phase A: load + classify ----
    uint4 v[4];
    #pragma unroll
    for (int j = 0; j < 4; j++) v[j] = sm4[blockBase + j * 256 + t];

    uint32_t cnt2 = 0, myc = 0;
    #pragma unroll
    for (int j = 0; j < 4; j++) {
        #pragma unroll
        for (int c = 0; c < 4; c++) {
            uint32_t u = (c == 0) ? v[j].x : (c == 1) ? v[j].y : (c == 2) ? v[j].z : v[j].w;
            cnt2 += (u >= P2);
            myc  += ((u - P1) < W);                // P1 <= u < P2 (u>=P1 since positive floats)
        }
    }

    // block prefix for candidate offsets: inclusive warp scan (ascending tid)
    uint32_t s = myc;
    #pragma unroll
    for (int off = 1; off < 32; off <<= 1) {
        uint32_t o = __shfl_up_sync(0xFFFFFFFFu, s, off);
        if (lane >= off) s += o;
    }
    if (lane == 31) wsum[w] = s;
    __syncthreads();
    if (t == 0) {
        uint32_t run = 0;
        #pragma unroll
        for (int i = 0; i < 8; i++) { uint32_t x = wsum[i]; wsum[i] = run; run += x; }
        sTot = run;
    }
    __syncthreads();
    uint32_t myoff = wsum[w] + (s - myc);          // exclusive prefix

    // write my candidates (0..3 typical)
    #pragma unroll
    for (int j = 0; j < 4; j++) {
        #pragma unroll
        for (int c = 0; c < 4; c++) {
            uint32_t u = (c == 0) ? v[j].x : (c == 1) ? v[j].y : (c == 2) ? v[j].z : v[j].w;
            if ((u - P1) < W) {
                if (myoff < CANDB) scand[myoff] = u;
                myoff++;
            }
        }
    }

    // reduce cnt2 (reuse hist[0..7] as scratch)
    #pragma unroll
    for (int off = 16; off > 0; off >>= 1)
        cnt2 += __shfl_down_sync(0xFFFFFFFFu, cnt2, off);
    if (lane == 0) hist[w] = cnt2;
    __syncthreads();

    if (t == 0) {
        uint32_t tot2 = 0;
        #pragma unroll
        for (int i = 0; i < 8; i++) tot2 += hist[i];
        atomicAdd(&g_c2[b], tot2);
        uint32_t n = sTot;
        if (n > CANDB) { g_of[b] = 1u; n = CANDB; }
        uint32_t base = atomicAdd(&g_nc[b], n);
        if (base + n > CANDCAP) g_of[b] = 1u;
        sBase = base;
    }
    __syncthreads();

    {
        uint32_t n = (sTot > CANDB) ? CANDB : sTot;
        uint32_t base = sBase;
        for (uint32_t i = t; i < n; i += 256)
            if (base + i < CANDCAP) g_cand[b * CANDCAP + base + i] = scand[i];
    }

    // ---- ticket: last block of this batch runs the threshold select ----
    __threadfence();
    __shared__ uint32_t sLast;
    if (t == 0) sLast = (atomicAdd(&g_tick[b], 1u) == BPB - 1) ? 1u : 0u;
    __syncthreads();
    if (!sLast) return;
    __threadfence();                                // see other blocks' g_cand writes

    // ---- Phase B: exact radix select for rank (KSEL - c2) among candidates ----
    const uint32_t nc = g_nc[b];
    const uint32_t c2 = g_c2[b];
    const bool miss = (g_of[b] != 0u) || (c2 >= KSEL) || (c2 + nc < KSEL) || (nc > CANDCAP);

    const uint32_t* __restrict__ cand = g_cand + b * CANDCAP;
    const uint32_t* __restrict__ full =
        reinterpret_cast<const uint32_t*>(smap) + (size_t)b * NTOK;

    uint32_t Kcur = miss ? (uint32_t)KSEL : (uint32_t)KSEL - c2;
    uint32_t prefixVal = 0;

    const int shifts[3] = {21, 10, 0};
    const int nbitsA[3] = {11, 11, 10};

    #pragma unroll
    for (int r = 0; r < 3; r++) {
        const int shift = shifts[r];
        const int nbits = nbitsA[r];
        const int nbins = 1 << nbits;
        const int hishift = shift + nbits;          // 32 on round 0 (unused)

        for (int i = t; i < nbins; i += 256) hist[i] = 0u;
        __syncthreads();

        if (!miss) {
            for (uint32_t i = t; i < nc; i += 256) {
                uint32_t u = cand[i];
                bool match = (r == 0) || ((u >> hishift) == prefixVal);
                if (match) atomicAdd(&hist[(u >> shift) & (uint32_t)(nbins - 1)], 1u);
            }
        } else {
            for (int i = t; i < NTOK; i += 256) {
                uint32_t u = full[i];
                bool match = (r == 0) || ((u >> hishift) == prefixVal);
                if (match) atomicAdd(&hist[(u >> shift) & (uint32_t)(nbins - 1)], 1u);
            }
        }
        __syncthreads();

        const int bpt  = nbins >> 8;                // 8 or 4
        const int base = t * bpt;
        uint32_t p = 0;
        #pragma unroll
        for (int j = 0; j < 8; j++)
            if (j < bpt) p += hist[base + j];
        uint32_t sfx = suffix_excl_256(p, wsum);    // bins above my chunk
        for (int j = bpt - 1; j >= 0; j--) {
            uint32_t h = hist[base + j];
            uint32_t s_incl = sfx + h;
            if (sfx < Kcur && s_incl >= Kcur) { sBin = (uint32_t)(base + j); sK = Kcur - sfx; }
            sfx = s_incl;
        }
        __syncthreads();
        prefixVal = (prefixVal << nbits) | sBin;
        Kcur = sK;
        __syncthreads();
    }

    if (t == 0) { g_T[b] = prefixVal; g_req[b] = Kcur; }
}

// ============================================================================
// Kernel 2: loss sweep (67 MB scores+gumbel DRAM + 16 MB smap, L2-hot).
// term = min(c + max(d,0) - sel*d, 100), c = ln(1+e^{-|d|}).
// ============================================================================
__global__ __launch_bounds__(256) void loss_kernel(const float4* __restrict__ zs4,
                                                   const uint4*  __restrict__ sm4,
                                                   const float4* __restrict__ gn4,
                                                   float* __restrict__ out,
                                                   unsigned nblocks) {
    __shared__ double wpart[8];
    const int t    = threadIdx.x;
    const int lane = t & 31;
    const int w    = t >> 5;
    const int b    = blockIdx.x >> 4;               // 16 blocks per batch
    const int blockBase = blockIdx.x * 1024;
    const uint32_t T = g_T[b];

    uint4  u[4];
    float4 za[4], zb[4], ga[4], gb[4];
    #pragma unroll
    for (int j = 0; j < 4; j++) {
        const int g = blockBase + j * 256 + t;
        u[j]  = sm4[g];
        za[j] = __ldcs(&zs4[2 * g]);
        zb[j] = __ldcs(&zs4[2 * g + 1]);
        ga[j] = __ldcs(&gn4[2 * g]);
        gb[j] = __ldcs(&gn4[2 * g + 1]);
    }

    float facc = 0.0f;
    #pragma unroll
    for (int j = 0; j < 4; j++) {
        float d0 = (za[j].x + ga[j].x) - (za[j].y + ga[j].y);
        float d1 = (za[j].z + ga[j].z) - (za[j].w + ga[j].w);
        float d2 = (zb[j].x + gb[j].x) - (zb[j].y + gb[j].y);
        float d3 = (zb[j].z + gb[j].z) - (zb[j].w + gb[j].w);
        #pragma unroll
        for (int c = 0; c < 4; c++) {
            float    d  = (c == 0) ? d0 : (c == 1) ? d1 : (c == 2) ? d2 : d3;
            uint32_t uu = (c == 0) ? u[j].x : (c == 1) ? u[j].y : (c == 2) ? u[j].z : u[j].w;
            bool sel;
            if (uu > T)       sel = true;
            else if (uu == T) sel = (atomicAdd(&g_eqcnt[b], 1u) < g_req[b]);  // rare
            else              sel = false;
            float cterm = __logf(1.0f + __expf(-fabsf(d)));
            float vterm = cterm + fmaxf(d, 0.0f) - (sel ? d : 0.0f);
            facc += fminf(vterm, 100.0f);
        }
    }

    double acc = (double)facc;
    #pragma unroll
    for (int off = 16; off > 0; off >>= 1)
        acc += __shfl_down_sync(0xFFFFFFFFu, acc, off);
    if (lane == 0) wpart[w] = acc;
    __syncthreads();

    if (t == 0) {
        double bsum = 0.0;
        #pragma unroll
        for (int i = 0; i < 8; i++) bsum += wpart[i];
        atomicAdd(&g_acc, bsum);
        __threadfence();
        unsigned ticket = atomicAdd(&g_done, 1u);
        if (ticket == nblocks - 1) {                 // last block: finalize + reset
            __threadfence();
            out[0] = (float)atomicAdd(&g_acc, 0.0);
            #pragma unroll 4
            for (int i = 0; i < BATCH; i++) {
                g_c2[i] = 0u; g_nc[i] = 0u; g_of[i] = 0u;
                g_eqcnt[i] = 0u; g_tick[i] = 0u;
            }
            g_acc = 0.0;
            __threadfence();
            g_done = 0u;
        }
    }
}

extern "C" void kernel_launch(void* const* d_in, const int* in_sizes, int n_in,
                              void* d_out, int out_size) {
    const float* scores = (const float*)d_in[0];   // [B, N, 2]
    const float* smap   = (const float*)d_in[1];   // [B, 1, H, W] == [B, N]
    const float* gumb   = (const float*)d_in[2];   // [B, N, 2]
    float* out = (float*)d_out;

    gather_thresh_kernel<<<GBLK, 256>>>((const uint4*)smap, smap);
    loss_kernel<<<1024, 256>>>((const float4*)scores, (const uint4*)smap,
                               (const float4*)gumb, out, 1024u);
}

// round 6
// speedup vs baseline: 1.2510x; 1.2510x over previous
#include <cuda_runtime.h>
#include <cstdint>

#define BATCH 64
#define NTOK  65536            // 256*256
#define KSEL  16384
#define TOTAL (BATCH * NTOK)
#define CANDCAP 4096           // per-batch candidate capacity (global)
#define CANDB   384            // per-block candidate capacity (smem)

// ---- device scratch (device globals; no allocations) ----
__device__ uint32_t g_cand[BATCH * CANDCAP];
__device__ uint32_t g_nc[BATCH];     // candidate counts (zero-init; reset by finalize)
__device__ uint32_t g_c2[BATCH];     // counts >= P2     (zero-init; reset by finalize)
__device__ uint32_t g_of[BATCH];     // overflow flags   (zero-init; reset by finalize)
__device__ uint32_t g_T[BATCH];      // threshold bit pattern
__device__ uint32_t g_req[BATCH];    // #(==T) to include
__device__ uint32_t g_eqcnt[BATCH];  // runtime tie counter
__device__ double   g_acc;           // loss accumulator
__device__ unsigned g_done;          // finalize ticket

#define P1F 0.73f
#define P2F 0.77f

// ============================================================================
// Kernel 1: smap sweep (16 MB): per batch count u>=P2 and gather P1<=u<P2
// candidates via a block prefix-scan. Zero hot-path atomics.
// 1024 blocks (16/batch) x 256 thr x 4 uint4/thread.
// ============================================================================
__global__ __launch_bounds__(256) void gather_kernel(const uint4* __restrict__ sm4) {
    __shared__ uint32_t scand[CANDB];
    __shared__ uint32_t wsum[8];
    __shared__ uint32_t sc2[8];
    __shared__ uint32_t sTot, sBase;

    const int t    = threadIdx.x;
    const int lane = t & 31;
    const int w    = t >> 5;
    const int b    = blockIdx.x >> 4;              // 16 blocks per batch
    const int blockBase = blockIdx.x * 1024;       // uint4-group base

    const uint32_t P1 = __float_as_uint(P1F);
    const uint32_t P2 = __float_as_uint(P2F);
    const uint32_t W  = P2 - P1;                   // window width in bit space

    uint4 v[4];
    #pragma unroll
    for (int j = 0; j < 4; j++) v[j] = sm4[blockBase + j * 256 + t];

    uint32_t cnt2 = 0, myc = 0;
    #pragma unroll
    for (int j = 0; j < 4; j++) {
        #pragma unroll
        for (int c = 0; c < 4; c++) {
            uint32_t u = (c == 0) ? v[j].x : (c == 1) ? v[j].y : (c == 2) ? v[j].z : v[j].w;
            cnt2 += (u >= P2);
            myc  += ((u - P1) < W);                // P1 <= u < P2 (positive floats)
        }
    }

    // inclusive warp scan of myc (ascending lane), then warp bases
    uint32_t s = myc;
    #pragma unroll
    for (int off = 1; off < 32; off <<= 1) {
        uint32_t o = __shfl_up_sync(0xFFFFFFFFu, s, off);
        if (lane >= off) s += o;
    }
    if (lane == 31) wsum[w] = s;
    // fold cnt2 reduction into the same sync window
    #pragma unroll
    for (int off = 16; off > 0; off >>= 1)
        cnt2 += __shfl_down_sync(0xFFFFFFFFu, cnt2, off);
    if (lane == 0) sc2[w] = cnt2;
    __syncthreads();

    if (t == 0) {
        uint32_t run = 0, tot2 = 0;
        #pragma unroll
        for (int i = 0; i < 8; i++) {
            uint32_t x = wsum[i]; wsum[i] = run; run += x;
            tot2 += sc2[i];
        }
        sTot = run;
        atomicAdd(&g_c2[b], tot2);
        uint32_t n = run;
        if (n > CANDB) { g_of[b] = 1u; n = CANDB; }
        uint32_t base = atomicAdd(&g_nc[b], n);
        if (base + n > CANDCAP) g_of[b] = 1u;
        sBase = base;
    }
    __syncthreads();

    uint32_t myoff = wsum[w] + (s - myc);          // exclusive block prefix
    #pragma unroll
    for (int j = 0; j < 4; j++) {
        #pragma unroll
        for (int c = 0; c < 4; c++) {
            uint32_t u = (c == 0) ? v[j].x : (c == 1) ? v[j].y : (c == 2) ? v[j].z : v[j].w;
            if ((u - P1) < W) {
                if (myoff < CANDB) scand[myoff] = u;
                myoff++;
            }
        }
    }
    __syncthreads();

    uint32_t n = (sTot > CANDB) ? CANDB : sTot;
    uint32_t base = sBase;
    for (uint32_t i = t; i < n; i += 256)
        if (base + i < CANDCAP) g_cand[b * CANDCAP + base + i] = scand[i];
}

// ============================================================================
// Kernel 2: per-batch exact threshold among candidates (L2-hot).
// Full-radix fallback over smap on window miss (never taken at this input).
// ============================================================================
__device__ __forceinline__ uint32_t suffix_excl_512(uint32_t v, uint32_t* wsum) {
    const int t = threadIdx.x, lane = t & 31, w = t >> 5;
    uint32_t s = v;
    #pragma unroll
    for (int off = 1; off < 32; off <<= 1) {
        uint32_t o = __shfl_down_sync(0xFFFFFFFFu, s, off);
        if (lane + off < 32) s += o;
    }
    if (lane == 0) wsum[w] = s;
    __syncthreads();
    if (t < 32) {
        uint32_t x  = (t < 16) ? wsum[t] : 0u;
        uint32_t sx = x;
        #pragma unroll
        for (int off = 1; off < 16; off <<= 1) {
            uint32_t o = __shfl_down_sync(0xFFFFFFFFu, sx, off);
            if (t + off < 16) sx += o;
        }
        if (t < 16) wsum[t] = sx - x;
    }
    __syncthreads();
    return wsum[w] + (s - v);
}

__global__ __launch_bounds__(512) void thresh_kernel(const float* __restrict__ smap) {
    __shared__ uint32_t hist[2048];
    __shared__ uint32_t wsum[32];
    __shared__ uint32_t sBin, sK;

    const int b = blockIdx.x;
    const int t = threadIdx.x;

    const uint32_t nc = g_nc[b];
    const uint32_t c2 = g_c2[b];
    const bool miss = (g_of[b] != 0u) || (c2 >= KSEL) || (c2 + nc < KSEL) || (nc > CANDCAP);

    const uint32_t* __restrict__ cand = g_cand + b * CANDCAP;
    const uint32_t* __restrict__ full =
        reinterpret_cast<const uint32_t*>(smap) + (size_t)b * NTOK;

    uint32_t Kcur = miss ? (uint32_t)KSEL : (uint32_t)KSEL - c2;
    uint32_t prefixVal = 0;

    const int shifts[3] = {21, 10, 0};
    const int nbitsA[3] = {11, 11, 10};

    #pragma unroll
    for (int r = 0; r < 3; r++) {
        const int shift = shifts[r];
        const int nbits = nbitsA[r];
        const int nbins = 1 << nbits;
        const int hishift = shift + nbits;          // 32 on round 0 (unused)

        for (int i = t; i < nbins; i += 512) hist[i] = 0u;
        __syncthreads();

        if (!miss) {
            for (uint32_t i = t; i < nc; i += 512) {
                uint32_t u = cand[i];
                bool match = (r == 0) || ((u >> hishift) == prefixVal);
                if (match) atomicAdd(&hist[(u >> shift) & (uint32_t)(nbins - 1)], 1u);
            }
        } else {
            for (int i = t; i < NTOK; i += 512) {
                uint32_t u = full[i];
                bool match = (r == 0) || ((u >> hishift) == prefixVal);
                if (match) atomicAdd(&hist[(u >> shift) & (uint32_t)(nbins - 1)], 1u);
            }
        }
        __syncthreads();

        const int bpt  = nbins >> 9;                // 4 or 2
        const int base = t * bpt;
        uint32_t p = 0;
        #pragma unroll
        for (int j = 0; j < 4; j++)
            if (j < bpt) p += hist[base + j];
        uint32_t sfx = suffix_excl_512(p, wsum);
        for (int j = bpt - 1; j >= 0; j--) {
            uint32_t h = hist[base + j];
            uint32_t s_incl = sfx + h;
            if (sfx < Kcur && s_incl >= Kcur) { sBin = (uint32_t)(base + j); sK = Kcur - sfx; }
            sfx = s_incl;
        }
        __syncthreads();
        prefixVal = (prefixVal << nbits) | sBin;
        Kcur = sK;
        __syncthreads();
    }

    if (t == 0) { g_T[b] = prefixVal; g_req[b] = Kcur; }
}

// ============================================================================
// Kernel 3: loss sweep (67 MB scores+gumbel DRAM + 16 MB smap, L2-hot).
// term = min(c + max(x,0), 100), x = sel ? -d : d, c = ln(1+e^{-|d|}).
// 2048 blocks x 256 thr x 2 groups/thread -> ~10 LDG.128/thread, modest regs.
// ============================================================================
__global__ __launch_bounds__(256) void loss_kernel(const float4* __restrict__ zs4,
                                                   const uint4*  __restrict__ sm4,
                                                   const float4* __restrict__ gn4,
                                                   float* __restrict__ out,
                                                   unsigned nblocks) {
    __shared__ double wpart[8];
    const int t    = threadIdx.x;
    const int lane = t & 31;
    const int w    = t >> 5;
    const int b    = blockIdx.x >> 5;               // 32 blocks per batch
    const int blockBase = blockIdx.x * 512;
    const uint32_t T = g_T[b];

    const int g0 = blockBase + t;
    const int g1 = blockBase + 256 + t;

    uint4  u0 = sm4[g0],                u1 = sm4[g1];
    float4 za0 = __ldcs(&zs4[2 * g0]),  zb0 = __ldcs(&zs4[2 * g0 + 1]);
    float4 za1 = __ldcs(&zs4[2 * g1]),  zb1 = __ldcs(&zs4[2 * g1 + 1]);
    float4 ga0 = __ldcs(&gn4[2 * g0]),  gb0 = __ldcs(&gn4[2 * g0 + 1]);
    float4 ga1 = __ldcs(&gn4[2 * g1]),  gb1 = __ldcs(&gn4[2 * g1 + 1]);

    float d[8];
    d[0] = (za0.x + ga0.x) - (za0.y + ga0.y);
    d[1] = (za0.z + ga0.z) - (za0.w + ga0.w);
    d[2] = (zb0.x + gb0.x) - (zb0.y + gb0.y);
    d[3] = (zb0.z + gb0.z) - (zb0.w + gb0.w);
    d[4] = (za1.x + ga1.x) - (za1.y + ga1.y);
    d[5] = (za1.z + ga1.z) - (za1.w + ga1.w);
    d[6] = (zb1.x + gb1.x) - (zb1.y + gb1.y);
    d[7] = (zb1.z + gb1.z) - (zb1.w + gb1.w);

    uint32_t uu[8] = {u0.x, u0.y, u0.z, u0.w, u1.x, u1.y, u1.z, u1.w};

    float facc = 0.0f;
    #pragma unroll
    for (int k = 0; k < 8; k++) {
        bool sel;
        if (uu[k] > T)       sel = true;
        else if (uu[k] == T) sel = (atomicAdd(&g_eqcnt[b], 1u) < g_req[b]);  // rare
        else                 sel = false;
        float x = sel ? -d[k] : d[k];
        float c = __logf(1.0f + __expf(-fabsf(x)));
        facc += fminf(c + fmaxf(x, 0.0f), 100.0f);
    }

    double acc = (double)facc;
    #pragma unroll
    for (int off = 16; off > 0; off >>= 1)
        acc += __shfl_down_sync(0xFFFFFFFFu, acc, off);
    if (lane == 0) wpart[w] = acc;
    __syncthreads();

    if (t == 0) {
        double bsum = 0.0;
        #pragma unroll
        for (int i = 0; i < 8; i++) bsum += wpart[i];
        atomicAdd(&g_acc, bsum);
        __threadfence();
        unsigned ticket = atomicAdd(&g_done, 1u);
        if (ticket == nblocks - 1) {                 // last block: finalize + reset
            __threadfence();
            out[0] = (float)atomicAdd(&g_acc, 0.0);
            #pragma unroll 4
            for (int i = 0; i < BATCH; i++) {
                g_c2[i] = 0u; g_nc[i] = 0u; g_of[i] = 0u; g_eqcnt[i] = 0u;
            }
            g_acc = 0.0;
            __threadfence();
            g_done = 0u;
        }
    }
}

extern "C" void kernel_launch(void* const* d_in, const int* in_sizes, int n_in,
                              void* d_out, int out_size) {
    const float* scores = (const float*)d_in[0];   // [B, N, 2]
    const float* smap   = (const float*)d_in[1];   // [B, 1, H, W] == [B, N]
    const float* gumb   = (const float*)d_in[2];   // [B, N, 2]
    float* out = (float*)d_out;

    gather_kernel<<<1024, 256>>>((const uint4*)smap);
    thresh_kernel<<<BATCH, 512>>>(smap);
    loss_kernel<<<2048, 256>>>((const float4*)scores, (const uint4*)smap,
                               (const float4*)gumb, out, 2048u);
}